// round 10
// baseline (speedup 1.0000x reference)
#include <cuda_runtime.h>
#include <cuda_bf16.h>
#include <cstdint>

// Problem constants: N=512, B=256, F=400, D=14, K=2
#define GS_B 256
#define GS_F 400
#define GS_BF (GS_B * GS_F)      // 102400 images
#define GS_D 14
#define GS_DD (GS_D * GS_D)      // 196 pixels/image
#define GS_K 2

#define IMS 4                    // images per block
#define NTB 196                  // threads/block: 4 images * 49 uint4
#define GRID (GS_BF / IMS)       // 25600 blocks

__device__ __forceinline__ float ex2f(float x) {
    float y;
    asm("ex2.approx.f32 %0, %1;" : "=f"(y) : "f"(x));
    return y;
}

// Separable-table kernel:
//   value(x,y) = bg + gx0[x]*gy0c[y] + gx1[x]*gy1c[y]
// where gyc folds the normalization c = h/(2*pi*w^2).
// Block = 4 whole images; thread = one uint4 (4 flat pixels) -> direct STG.128.
__global__ __launch_bounds__(NTB) void gs_sep(
    const int*          __restrict__ batch_idx,   // (B,)
    const unsigned int* __restrict__ m_mask,      // (B,F,K)
    const float*        __restrict__ height,      // (B,F,K)
    const float*        __restrict__ width,       // (B,F,K)
    const float*        __restrict__ x0,          // (B,F,K)
    const float*        __restrict__ y0,          // (B,F,K)
    const float*        __restrict__ background,  // (B,F)
    const float*        __restrict__ target_locs, // (N,F,2)
    float*              __restrict__ out)         // (B,F,D,D)
{
    __shared__ float2 sgy[IMS][GS_D];   // (gy0c, gy1c) per y
    __shared__ float2 sgx[IMS][GS_D];   // (gx0,  gx1 ) per x
    __shared__ float4 sdig[IMS][GS_K];  // (sx, sy, aL, l2c)
    __shared__ float  sbg[IMS];

    const int t = threadIdx.x;

    // ---- Phase A1: digests (8 lanes) + backgrounds (4 lanes) ----
    if (t < 2 * IMS) {
        const int iml = t >> 1;
        const int k   = t & 1;
        const int bf  = blockIdx.x * IMS + iml;
        const int b   = bf / GS_F;
        const int f   = bf - b * GS_F;

        const int   bi  = __ldg(&batch_idx[b]);
        const int   tlo = (bi * GS_F + f) * 2;
        const float tlx = __ldg(&target_locs[tlo]);
        const float tly = __ldg(&target_locs[tlo + 1]);

        const int i = bf * GS_K + k;
        const unsigned int m = __ldg(&m_mask[i]);
        const float h = (m != 0u) ? __ldg(&height[i]) : 0.0f;
        const float w = __ldg(&width[i]);
        const float invw2 = __fdividef(1.0f, w * w);

        const float HALF_LOG2E = 0.7213475204444817f;   // 0.5*log2(e)
        const float INV_2PI    = 0.15915494309189535f;

        const float aL  = -HALF_LOG2E * invw2;
        const float l2c = __log2f(h * INV_2PI * invw2); // h==0 -> -inf -> table 0
        const float sx  = tlx + __ldg(&x0[i]);
        const float sy  = tly + __ldg(&y0[i]);
        sdig[iml][k] = make_float4(sx, sy, aL, l2c);
    } else if (t < 2 * IMS + IMS) {
        const int iml = t - 2 * IMS;
        sbg[iml] = __ldg(&background[blockIdx.x * IMS + iml]);
    }
    __syncthreads();

    // ---- Phase A2: 112 table entries, one float2 (both spots) each ----
    if (t < IMS * 2 * GS_D) {               // 112
        const int iml  = t / (2 * GS_D);    // image 0..3
        const int r    = t - iml * 2 * GS_D;
        const int axis = r / GS_D;          // 0 = gy (with c), 1 = gx
        const int u    = r - axis * GS_D;
        const float fu = (float)u;

        const float4 d0 = sdig[iml][0];
        const float4 d1 = sdig[iml][1];

        float v0, v1;
        if (axis == 0) {
            const float t0 = fu - d0.y, t1 = fu - d1.y;
            v0 = ex2f(fmaf(d0.z * t0, t0, d0.w));
            v1 = ex2f(fmaf(d1.z * t1, t1, d1.w));
            sgy[iml][u] = make_float2(v0, v1);
        } else {
            const float t0 = fu - d0.x, t1 = fu - d1.x;
            v0 = ex2f(d0.z * t0 * t0);
            v1 = ex2f(d1.z * t1 * t1);
            sgx[iml][u] = make_float2(v0, v1);
        }
    }
    __syncthreads();

    // ---- Phase B: 4 pixels per thread, direct coalesced store ----
    const int il  = t / 49;                 // image within block
    const int rem = t - il * 49;            // uint4 within image
    const int i0  = rem * 4;                // first flat pixel (0..192)

    int x = i0 / GS_D;
    int y = i0 - x * GS_D;
    const float bg = sbg[il];

    float acc[4];
#pragma unroll
    for (int q = 0; q < 4; ++q) {
        const float2 gy = sgy[il][y];
        const float2 gx = sgx[il][x];
        acc[q] = fmaf(gx.y, gy.y, fmaf(gx.x, gy.x, bg));
        // advance flat pixel with row wrap
        ++y;
        if (y == GS_D) { y = 0; ++x; }
    }

    reinterpret_cast<float4*>(out)[(size_t)blockIdx.x * NTB + t] =
        make_float4(acc[0], acc[1], acc[2], acc[3]);
}

extern "C" void kernel_launch(void* const* d_in, const int* in_sizes, int n_in,
                              void* d_out, int out_size) {
    const int*          batch_idx   = (const int*)d_in[0];
    const unsigned int* m_mask      = (const unsigned int*)d_in[1];
    const float*        height      = (const float*)d_in[2];
    const float*        width       = (const float*)d_in[3];
    const float*        x0          = (const float*)d_in[4];
    const float*        y0          = (const float*)d_in[5];
    const float*        background  = (const float*)d_in[6];
    const float*        target_locs = (const float*)d_in[7];
    // d_in[8] = pixel_pos: integer grid, regenerated analytically

    float* out = (float*)d_out;

    gs_sep<<<GRID, NTB>>>(batch_idx, m_mask, height, width,
                          x0, y0, background, target_locs, out);
}

// round 11
// speedup vs baseline: 2.1611x; 2.1611x over previous
#include <cuda_runtime.h>
#include <cuda_bf16.h>
#include <cstdint>

// Problem constants: N=512, B=256, F=400, D=14, K=2
#define GS_B 256
#define GS_F 400
#define GS_BF (GS_B * GS_F)      // 102400 images
#define GS_D 14
#define GS_DD (GS_D * GS_D)      // 196
#define GS_K 2

#define BFS 32                   // images per tile
#define NT (BFS * GS_D)          // 448 threads = 14 warps
#define NTILES (GS_BF / BFS)     // 3200 tiles
#define GRIDP 592                // 148 SMs * 4 CTAs: persistent grid

typedef unsigned long long ull;

__device__ __forceinline__ float ex2f(float x) {
    float y;
    asm("ex2.approx.f32 %0, %1;" : "=f"(y) : "f"(x));
    return y;
}

#define PACK2(d, lo, hi) \
    asm("mov.b64 %0, {%1, %2};" : "=l"(d) : "f"(lo), "f"(hi))
#define MUL2(d, a, b) \
    asm("mul.rn.f32x2 %0, %1, %2;" : "=l"(d) : "l"(a), "l"(b))
#define ADD2(d, a, b) \
    asm("add.rn.f32x2 %0, %1, %2;" : "=l"(d) : "l"(a), "l"(b))

// Digest for one (image, spot) of a tile -> two float4 rows in smem.
__device__ __forceinline__ void do_digest(
    int tile, int pidx, float4 (*sd)[4],
    const int*          __restrict__ batch_idx,
    const unsigned int* __restrict__ m_mask,
    const float*        __restrict__ height,
    const float*        __restrict__ width,
    const float*        __restrict__ x0,
    const float*        __restrict__ y0,
    const float*        __restrict__ background,
    const float*        __restrict__ target_locs)
{
    const int iml = pidx >> 1;
    const int k   = pidx & 1;
    const int bf  = tile * BFS + iml;
    const int b   = bf / GS_F;
    const int f   = bf - b * GS_F;

    const int   bi  = __ldg(&batch_idx[b]);
    const int   tlo = (bi * GS_F + f) * 2;
    const float tlx = __ldg(&target_locs[tlo]);
    const float tly = __ldg(&target_locs[tlo + 1]);

    const int i = bf * GS_K + k;
    const unsigned int m = __ldg(&m_mask[i]);
    const float h = (m != 0u) ? __ldg(&height[i]) : 0.0f;
    const float w = __ldg(&width[i]);
    const float invw2 = __fdividef(1.0f, w * w);

    const float HALF_LOG2E = 0.7213475204444817f;   // 0.5*log2(e)
    const float INV_2PI    = 0.15915494309189535f;

    const float aL  = -HALF_LOG2E * invw2;           // log2-domain scale
    const float l2c = __log2f(h * INV_2PI * invw2);  // h==0 -> -inf -> e==0
    const float sx  = tlx + __ldg(&x0[i]);
    const float sy  = tly + __ldg(&y0[i]);

    const float base2 = fmaf(aL * sy, sy, l2c);
    const float v0 = ex2f(aL * (1.0f - 2.0f * sy));
    const float V  = ex2f(2.0f * aL);
    const float v1 = v0 * V;
    const float v2 = v1 * V;
    const float V2 = V * V;
    const float bgv = (k == 0) ? __ldg(&background[bf]) : 0.0f;

    sd[iml][2 * k]     = make_float4(sx, aL, base2, v0);
    sd[iml][2 * k + 1] = make_float4(v0 * v1, v1 * v2, V2 * V2, bgv);
}

// Persistent kernel: each block loops over tiles stride-GRIDP, digesting
// tile i+1 (buffer ^1) while evaluating/storing tile i (buffer p).
__global__ __launch_bounds__(NT, 4) void gs_persist(
    const int*          __restrict__ batch_idx,
    const unsigned int* __restrict__ m_mask,
    const float*        __restrict__ height,
    const float*        __restrict__ width,
    const float*        __restrict__ x0,
    const float*        __restrict__ y0,
    const float*        __restrict__ background,
    const float*        __restrict__ target_locs,
    float*              __restrict__ out)
{
    __shared__ __align__(16) float4 sdig[2][BFS][4];   // 4 KB (double buffer)
    __shared__ __align__(16) float  sbuf[NT * GS_D];   // 24.5 KB staging

    const int t    = threadIdx.x;
    const int wid  = t >> 5;
    const int lane = t & 31;
    const int pidx = wid * 5 + lane;           // digest slot (lanes 0..4)
    const bool dig = (lane < 5) && (pidx < 2 * BFS);

    const int bfl = t / GS_D;                  // image within tile
    const int px  = t - bfl * GS_D;            // row within image
    const float fpx = (float)px;
    const int wbase = wid * 32;

    int tile = blockIdx.x;
    int parity = 0;

    // prologue: digest first tile into buffer 0
    if (tile < NTILES && dig)
        do_digest(tile, pidx, sdig[0], batch_idx, m_mask, height, width,
                  x0, y0, background, target_locs);

    while (tile < NTILES) {
        __syncthreads();                       // sdig[parity] ready

        const int next = tile + GRIDP;
        if (next < NTILES && dig)
            do_digest(next, pidx, sdig[parity ^ 1], batch_idx, m_mask, height,
                      width, x0, y0, background, target_locs);

        // ---- Phase B: packed f32x2 row recurrence from sdig[parity] ----
        const float4* pp = &sdig[parity][bfl][0];
        const float4 p0 = pp[0];
        const float4 p1 = pp[1];
        const float4 p2 = pp[2];
        const float4 p3 = pp[3];

        ull A[7];
        ull bgp; PACK2(bgp, p1.w, p1.w);

        // spot 0
        {
            const float dx = fpx - p0.x;
            const float e0 = ex2f(fmaf(p0.y * dx, dx, p0.z));
            const float e1 = e0 * p0.w;
            ull E; PACK2(E, e0, e1);
            ull P; PACK2(P, p1.x, p1.y);
            ull Vp; PACK2(Vp, p1.z, p1.z);
#pragma unroll
            for (int j = 0; j < 7; ++j) {
                ADD2(A[j], bgp, E);
                if (j < 6) { MUL2(E, E, P); MUL2(P, P, Vp); }
            }
        }
        // spot 1
        {
            const float dx = fpx - p2.x;
            const float e0 = ex2f(fmaf(p2.y * dx, dx, p2.z));
            const float e1 = e0 * p2.w;
            ull E; PACK2(E, e0, e1);
            ull P; PACK2(P, p3.x, p3.y);
            ull Vp; PACK2(Vp, p3.z, p3.z);
#pragma unroll
            for (int j = 0; j < 7; ++j) {
                ADD2(A[j], A[j], E);
                if (j < 6) { MUL2(E, E, P); MUL2(P, P, Vp); }
            }
        }

        // stage row into warp-local smem span
        ull* sp = reinterpret_cast<ull*>(&sbuf[t * GS_D]);
#pragma unroll
        for (int j = 0; j < 7; ++j) sp[j] = A[j];

        __syncwarp();

        // warp's 32 rows are contiguous in gmem: coalesced STG.128
        const uint4* sl = reinterpret_cast<const uint4*>(&sbuf[wbase * GS_D]);
        uint4* og = reinterpret_cast<uint4*>(out)
                  + (size_t)tile * (BFS * GS_DD / 4) + wid * 112;
        og[lane]      = sl[lane];
        og[lane + 32] = sl[lane + 32];
        og[lane + 64] = sl[lane + 64];
        if (lane < 16) og[lane + 96] = sl[lane + 96];

        __syncwarp();                          // protect sbuf reuse next tile

        tile = next;
        parity ^= 1;
    }
}

extern "C" void kernel_launch(void* const* d_in, const int* in_sizes, int n_in,
                              void* d_out, int out_size) {
    const int*          batch_idx   = (const int*)d_in[0];
    const unsigned int* m_mask      = (const unsigned int*)d_in[1];
    const float*        height      = (const float*)d_in[2];
    const float*        width       = (const float*)d_in[3];
    const float*        x0          = (const float*)d_in[4];
    const float*        y0          = (const float*)d_in[5];
    const float*        background  = (const float*)d_in[6];
    const float*        target_locs = (const float*)d_in[7];
    // d_in[8] = pixel_pos: integer grid, regenerated analytically

    float* out = (float*)d_out;

    gs_persist<<<GRIDP, NT>>>(batch_idx, m_mask, height, width,
                              x0, y0, background, target_locs, out);
}

// round 12
// speedup vs baseline: 2.3961x; 1.1088x over previous
#include <cuda_runtime.h>
#include <cuda_bf16.h>
#include <cstdint>

// Problem constants: N=512, B=256, F=400, D=14, K=2
#define GS_B 256
#define GS_F 400
#define GS_BF (GS_B * GS_F)      // 102400 images
#define GS_D 14
#define GS_DD (GS_D * GS_D)      // 196
#define GS_K 2

#define BFS 32                   // images per tile
#define NT (BFS * GS_D)          // 448 threads = 14 warps
#define TPB 5                    // tiles per block
#define GRIDP (GS_BF / BFS / TPB) // 640 blocks * 5 tiles = 3200 tiles

typedef unsigned long long ull;

__device__ __forceinline__ float ex2f(float x) {
    float y;
    asm("ex2.approx.f32 %0, %1;" : "=f"(y) : "f"(x));
    return y;
}

#define PACK2(d, lo, hi) \
    asm("mov.b64 %0, {%1, %2};" : "=l"(d) : "f"(lo), "f"(hi))
#define MUL2(d, a, b) \
    asm("mul.rn.f32x2 %0, %1, %2;" : "=l"(d) : "l"(a), "l"(b))
#define ADD2(d, a, b) \
    asm("add.rn.f32x2 %0, %1, %2;" : "=l"(d) : "l"(a), "l"(b))

// One kernel: batch-digest all 5 tiles up front (1 digest/thread, threads
// 0..319), ONE __syncthreads, then warps free-run 5 tile iterations with
// only warp-local synchronization.
__global__ __launch_bounds__(NT, 4) void gs_batch(
    const int*          __restrict__ batch_idx,   // (B,)
    const unsigned int* __restrict__ m_mask,      // (B,F,K)
    const float*        __restrict__ height,      // (B,F,K)
    const float*        __restrict__ width,       // (B,F,K)
    const float*        __restrict__ x0,          // (B,F,K)
    const float*        __restrict__ y0,          // (B,F,K)
    const float*        __restrict__ background,  // (B,F)
    const float*        __restrict__ target_locs, // (N,F,2)
    float*              __restrict__ out)         // (B,F,D,D)
{
    __shared__ __align__(16) float4 sdig[TPB][BFS][4];   // 10 KB
    __shared__ __align__(16) float  sbuf[NT * GS_D];     // 24.5 KB staging

    const int t    = threadIdx.x;
    const int wid  = t >> 5;
    const int lane = t & 31;
    const int tile0 = blockIdx.x * TPB;

    // ---- Phase A: 320 digests, one per thread, fully parallel ----
    if (t < TPB * BFS * GS_K) {
        const int tl  = t >> 6;            // tile-local 0..4
        const int r   = t & 63;
        const int iml = r >> 1;            // image within tile
        const int k   = r & 1;
        const int bf  = (tile0 + tl) * BFS + iml;
        const int b   = bf / GS_F;
        const int f   = bf - b * GS_F;

        const int   bi  = __ldg(&batch_idx[b]);
        const int   tlo = (bi * GS_F + f) * 2;
        const float tlx = __ldg(&target_locs[tlo]);
        const float tly = __ldg(&target_locs[tlo + 1]);

        const int i = bf * GS_K + k;
        const unsigned int m = __ldg(&m_mask[i]);
        const float h = (m != 0u) ? __ldg(&height[i]) : 0.0f;
        const float w = __ldg(&width[i]);
        const float invw2 = __fdividef(1.0f, w * w);

        const float HALF_LOG2E = 0.7213475204444817f;   // 0.5*log2(e)
        const float INV_2PI    = 0.15915494309189535f;

        const float aL  = -HALF_LOG2E * invw2;
        const float l2c = __log2f(h * INV_2PI * invw2); // h==0 -> -inf -> e==0
        const float sx  = tlx + __ldg(&x0[i]);
        const float sy  = tly + __ldg(&y0[i]);

        const float base2 = fmaf(aL * sy, sy, l2c);
        const float v0 = ex2f(aL * (1.0f - 2.0f * sy));
        const float V  = ex2f(2.0f * aL);
        const float v1 = v0 * V;
        const float v2 = v1 * V;
        const float V2 = V * V;
        const float bgv = (k == 0) ? __ldg(&background[bf]) : 0.0f;

        sdig[tl][iml][2 * k]     = make_float4(sx, aL, base2, v0);
        sdig[tl][iml][2 * k + 1] = make_float4(v0 * v1, v1 * v2, V2 * V2, bgv);
    }
    __syncthreads();     // the ONLY block barrier

    // ---- Phase B: 5 free-running tile iterations per warp ----
    const int bfl = t / GS_D;             // image within tile
    const int px  = t - bfl * GS_D;       // row within image
    const float fpx = (float)px;
    const int wbase = wid * 32;

    ull* sp = reinterpret_cast<ull*>(&sbuf[t * GS_D]);
    const uint4* sl = reinterpret_cast<const uint4*>(&sbuf[wbase * GS_D]);

#pragma unroll
    for (int tl = 0; tl < TPB; ++tl) {
        const float4* pp = &sdig[tl][bfl][0];
        const float4 p0 = pp[0];
        const float4 p1 = pp[1];
        const float4 p2 = pp[2];
        const float4 p3 = pp[3];

        ull A[7];
        ull bgp; PACK2(bgp, p1.w, p1.w);

        // spot 0
        {
            const float dx = fpx - p0.x;
            const float e0 = ex2f(fmaf(p0.y * dx, dx, p0.z));
            const float e1 = e0 * p0.w;
            ull E; PACK2(E, e0, e1);
            ull P; PACK2(P, p1.x, p1.y);
            ull Vp; PACK2(Vp, p1.z, p1.z);
#pragma unroll
            for (int j = 0; j < 7; ++j) {
                ADD2(A[j], bgp, E);
                if (j < 6) { MUL2(E, E, P); MUL2(P, P, Vp); }
            }
        }
        // spot 1
        {
            const float dx = fpx - p2.x;
            const float e0 = ex2f(fmaf(p2.y * dx, dx, p2.z));
            const float e1 = e0 * p2.w;
            ull E; PACK2(E, e0, e1);
            ull P; PACK2(P, p3.x, p3.y);
            ull Vp; PACK2(Vp, p3.z, p3.z);
#pragma unroll
            for (int j = 0; j < 7; ++j) {
                ADD2(A[j], A[j], E);
                if (j < 6) { MUL2(E, E, P); MUL2(P, P, Vp); }
            }
        }

        // warp-local staging
#pragma unroll
        for (int j = 0; j < 7; ++j) sp[j] = A[j];

        __syncwarp();

        // warp's 32 rows = contiguous 1792B in gmem: coalesced STG.128
        uint4* og = reinterpret_cast<uint4*>(out)
                  + (size_t)(tile0 + tl) * (BFS * GS_DD / 4) + wid * 112;
        og[lane]      = sl[lane];
        og[lane + 32] = sl[lane + 32];
        og[lane + 64] = sl[lane + 64];
        if (lane < 16) og[lane + 96] = sl[lane + 96];

        __syncwarp();    // protect sbuf reuse next iteration
    }
}

extern "C" void kernel_launch(void* const* d_in, const int* in_sizes, int n_in,
                              void* d_out, int out_size) {
    const int*          batch_idx   = (const int*)d_in[0];
    const unsigned int* m_mask      = (const unsigned int*)d_in[1];
    const float*        height      = (const float*)d_in[2];
    const float*        width       = (const float*)d_in[3];
    const float*        x0          = (const float*)d_in[4];
    const float*        y0          = (const float*)d_in[5];
    const float*        background  = (const float*)d_in[6];
    const float*        target_locs = (const float*)d_in[7];
    // d_in[8] = pixel_pos: integer grid, regenerated analytically

    float* out = (float*)d_out;

    gs_batch<<<GRIDP, NT>>>(batch_idx, m_mask, height, width,
                            x0, y0, background, target_locs, out);
}

// round 13
// speedup vs baseline: 2.5625x; 1.0694x over previous
#include <cuda_runtime.h>
#include <cuda_bf16.h>
#include <cstdint>

// Problem constants: N=512, B=256, F=400, D=14, K=2
#define GS_B 256
#define GS_F 400
#define GS_BF (GS_B * GS_F)      // 102400 images
#define GS_D 14
#define GS_DD (GS_D * GS_D)      // 196
#define GS_K 2

#define BFS 32                   // images per tile
#define NT (BFS * GS_D)          // 448 threads = 14 warps
#define NTILES (GS_BF / BFS)     // 3200 tiles
#define GRIDP 592                // 148 SMs * 4 CTAs: exactly one wave
#define MAXT 6                   // max tiles per block (ceil(3200/592))

typedef unsigned long long ull;

__device__ __forceinline__ float ex2f(float x) {
    float y;
    asm("ex2.approx.f32 %0, %1;" : "=f"(y) : "f"(x));
    return y;
}

#define PACK2(d, lo, hi) \
    asm("mov.b64 %0, {%1, %2};" : "=l"(d) : "f"(lo), "f"(hi))
#define MUL2(d, a, b) \
    asm("mul.rn.f32x2 %0, %1, %2;" : "=l"(d) : "l"(a), "l"(b))
#define ADD2(d, a, b) \
    asm("add.rn.f32x2 %0, %1, %2;" : "=l"(d) : "l"(a), "l"(b))

// Persistent, perfectly balanced: 592 blocks (one CTA wave), each owns
// tiles bid + j*592 (5 or 6). All digests for the block's tiles are
// computed in one parallel prologue (1 digest/thread), ONE __syncthreads,
// then warps free-run the tile loop with warp-local sync only.
__global__ __launch_bounds__(NT, 4) void gs_persist(
    const int*          __restrict__ batch_idx,   // (B,)
    const unsigned int* __restrict__ m_mask,      // (B,F,K)
    const float*        __restrict__ height,      // (B,F,K)
    const float*        __restrict__ width,       // (B,F,K)
    const float*        __restrict__ x0,          // (B,F,K)
    const float*        __restrict__ y0,          // (B,F,K)
    const float*        __restrict__ background,  // (B,F)
    const float*        __restrict__ target_locs, // (N,F,2)
    float*              __restrict__ out)         // (B,F,D,D)
{
    __shared__ __align__(16) float4 sdig[MAXT][BFS][4];   // 12 KB
    __shared__ __align__(16) float  sbuf[NT * GS_D];      // 24.5 KB staging

    const int t    = threadIdx.x;
    const int wid  = t >> 5;
    const int lane = t & 31;
    const int bid  = blockIdx.x;

    // ---- Phase A: up to 384 digests, one per thread, fully parallel ----
    if (t < MAXT * BFS * GS_K) {
        const int tl   = t >> 6;                 // tile slot 0..5
        const int tile = bid + tl * GRIDP;
        if (tile < NTILES) {
            const int r   = t & 63;
            const int iml = r >> 1;              // image within tile
            const int k   = r & 1;
            const int bf  = tile * BFS + iml;
            const int b   = bf / GS_F;
            const int f   = bf - b * GS_F;

            const int   bi  = __ldg(&batch_idx[b]);
            const int   tlo = (bi * GS_F + f) * 2;
            const float tlx = __ldg(&target_locs[tlo]);
            const float tly = __ldg(&target_locs[tlo + 1]);

            const int i = bf * GS_K + k;
            const unsigned int m = __ldg(&m_mask[i]);
            const float h = (m != 0u) ? __ldg(&height[i]) : 0.0f;
            const float w = __ldg(&width[i]);
            const float invw2 = __fdividef(1.0f, w * w);

            const float HALF_LOG2E = 0.7213475204444817f;   // 0.5*log2(e)
            const float INV_2PI    = 0.15915494309189535f;

            const float aL  = -HALF_LOG2E * invw2;
            const float l2c = __log2f(h * INV_2PI * invw2); // h==0 -> -inf
            const float sx  = tlx + __ldg(&x0[i]);
            const float sy  = tly + __ldg(&y0[i]);

            const float base2 = fmaf(aL * sy, sy, l2c);
            const float v0 = ex2f(aL * (1.0f - 2.0f * sy));
            const float V  = ex2f(2.0f * aL);
            const float v1 = v0 * V;
            const float v2 = v1 * V;
            const float V2 = V * V;
            const float bgv = (k == 0) ? __ldg(&background[bf]) : 0.0f;

            sdig[tl][iml][2 * k]     = make_float4(sx, aL, base2, v0);
            sdig[tl][iml][2 * k + 1] = make_float4(v0 * v1, v1 * v2, V2 * V2, bgv);
        }
    }
    __syncthreads();     // the ONLY block barrier

    // ---- Phase B: free-running tile loop per warp ----
    const int bfl = t / GS_D;             // image within tile
    const int px  = t - bfl * GS_D;       // row within image
    const float fpx = (float)px;
    const int wbase = wid * 32;

    ull* sp = reinterpret_cast<ull*>(&sbuf[t * GS_D]);
    const uint4* sl = reinterpret_cast<const uint4*>(&sbuf[wbase * GS_D]);

#pragma unroll
    for (int tl = 0; tl < MAXT; ++tl) {
        const int tile = bid + tl * GRIDP;
        if (tile >= NTILES) break;

        const float4* pp = &sdig[tl][bfl][0];
        const float4 p0 = pp[0];
        const float4 p1 = pp[1];
        const float4 p2 = pp[2];
        const float4 p3 = pp[3];

        ull A[7];
        ull bgp; PACK2(bgp, p1.w, p1.w);

        // spot 0
        {
            const float dx = fpx - p0.x;
            const float e0 = ex2f(fmaf(p0.y * dx, dx, p0.z));
            const float e1 = e0 * p0.w;
            ull E; PACK2(E, e0, e1);
            ull P; PACK2(P, p1.x, p1.y);
            ull Vp; PACK2(Vp, p1.z, p1.z);
#pragma unroll
            for (int j = 0; j < 7; ++j) {
                ADD2(A[j], bgp, E);
                if (j < 6) { MUL2(E, E, P); MUL2(P, P, Vp); }
            }
        }
        // spot 1
        {
            const float dx = fpx - p2.x;
            const float e0 = ex2f(fmaf(p2.y * dx, dx, p2.z));
            const float e1 = e0 * p2.w;
            ull E; PACK2(E, e0, e1);
            ull P; PACK2(P, p3.x, p3.y);
            ull Vp; PACK2(Vp, p3.z, p3.z);
#pragma unroll
            for (int j = 0; j < 7; ++j) {
                ADD2(A[j], A[j], E);
                if (j < 6) { MUL2(E, E, P); MUL2(P, P, Vp); }
            }
        }

        // warp-local staging
#pragma unroll
        for (int j = 0; j < 7; ++j) sp[j] = A[j];

        __syncwarp();

        // warp's 32 rows = contiguous 1792B span: coalesced STG.128
        uint4* og = reinterpret_cast<uint4*>(out)
                  + (size_t)tile * (BFS * GS_DD / 4) + wid * 112;
        og[lane]      = sl[lane];
        og[lane + 32] = sl[lane + 32];
        og[lane + 64] = sl[lane + 64];
        if (lane < 16) og[lane + 96] = sl[lane + 96];

        __syncwarp();    // protect sbuf reuse next iteration
    }
}

extern "C" void kernel_launch(void* const* d_in, const int* in_sizes, int n_in,
                              void* d_out, int out_size) {
    const int*          batch_idx   = (const int*)d_in[0];
    const unsigned int* m_mask      = (const unsigned int*)d_in[1];
    const float*        height      = (const float*)d_in[2];
    const float*        width       = (const float*)d_in[3];
    const float*        x0          = (const float*)d_in[4];
    const float*        y0          = (const float*)d_in[5];
    const float*        background  = (const float*)d_in[6];
    const float*        target_locs = (const float*)d_in[7];
    // d_in[8] = pixel_pos: integer grid, regenerated analytically

    float* out = (float*)d_out;

    gs_persist<<<GRIDP, NT>>>(batch_idx, m_mask, height, width,
                              x0, y0, background, target_locs, out);
}